// round 14
// baseline (speedup 1.0000x reference)
#include <cuda_runtime.h>
#include <cuda_fp16.h>
#include <mma.h>

using namespace nvcuda;

#define Mv    32768
#define Ev    262144
#define RANKv 5
#define FILTv 32
#define FINv  32
#define NBv   8
#define VEC   256   // FIN * NB

#define KCAP  96    // edge slots per chunk (block mean deg = 64, std ~8)
#define B_LD  264   // halfs per B-tile row (256 + 8 pad)
#define S_LD  104   // halfs per S row (96 + 8 pad)

typedef unsigned long long u64;
typedef unsigned int u32;

struct alignas(8) Edge { int c; float w; };

__device__ __half g_T[4][(size_t)Mv * VEC];
__device__ int    g_cnt[Mv];         // zero at module load; re-zeroed by k_scan1 each replay
__device__ int    g_rowptr[Mv];      // block-local exclusive scans
__device__ int    g_bsum[32];        // per-1024-chunk totals
__device__ int    g_pos[Ev];
__device__ Edge   g_edge[Ev];
__device__ __half g_W[160 * FILTv];  // W fp16, rows = kr*32+f

// warp-wide exclusive scan of g_bsum; base offset for chunk j (per-lane j ok)
__device__ __forceinline__ int chunk_base(int l, int j) {
    int own = g_bsum[l];
    int v = own;
#pragma unroll
    for (int off = 1; off < 32; off <<= 1) {
        int u = __shfl_up_sync(0xffffffffu, v, off);
        if (l >= off) v += u;
    }
    int excl = v - own;
    return __shfl_sync(0xffffffffu, excl, j & 31);
}

// row [start,end) bounds for row m, lane l (full-warp collective)
__device__ __forceinline__ void row_bounds(int m, int l, int& s, int& e) {
    int own = g_bsum[l];
    int v = own;
#pragma unroll
    for (int off = 1; off < 32; off <<= 1) {
        int u = __shfl_up_sync(0xffffffffu, v, off);
        if (l >= off) v += u;
    }
    int excl = v - own;
    s = __shfl_sync(0xffffffffu, excl, m >> 10) + g_rowptr[m];
    e = (m == Mv - 1) ? Ev
        : __shfl_sync(0xffffffffu, excl, ((m + 1) >> 10) & 31) + g_rowptr[m + 1];
}

// ---------------- CSR build ----------------
__global__ void k_hist(const int* __restrict__ rows) {
    int e = blockIdx.x * 256 + threadIdx.x;
    g_pos[e] = atomicAdd(&g_cnt[rows[e]], 1);
}

// grid 33: blocks 0..31 scan 1024-chunks of g_cnt (and re-zero); block 32 converts W
__global__ void k_scan1(const float* __restrict__ kern) {
    if (blockIdx.x == 32) {
        int t = threadIdx.x;
        for (int i = t; i < 160 * FILTv; i += 1024) {
            int row = i >> 5, filt = i & 31;
            int kr = row >> 5, f = row & 31;
            g_W[i] = __float2half_rn(kern[(f * RANKv + kr) * FILTv + filt]);
        }
        return;
    }
    __shared__ int sh[1024];
    int t = threadIdx.x;
    int i = blockIdx.x * 1024 + t;
    int c = g_cnt[i];
    g_cnt[i] = 0;
    sh[t] = c;
    __syncthreads();
#pragma unroll
    for (int off = 1; off < 1024; off <<= 1) {
        int v = (t >= off) ? sh[t - off] : 0;
        __syncthreads();
        sh[t] += v;
        __syncthreads();
    }
    g_rowptr[i] = sh[t] - c;
    if (t == 1023) g_bsum[blockIdx.x] = sh[t];
}

// fused: blocks [0,1024) build edge array; blocks [1024,5120) transpose x -> T0 fp16
__global__ void __launch_bounds__(256) k_scatter_init(const int* __restrict__ rows,
                                                      const int* __restrict__ cols,
                                                      const float* __restrict__ vals,
                                                      const float* __restrict__ x) {
    int t = threadIdx.x;
    int l = t & 31;
    if (blockIdx.x < 1024) {
        int e = blockIdx.x * 256 + t;
        int r = rows[e];
        int base = chunk_base(l, r >> 10);
        int idx = base + g_rowptr[r] + g_pos[e];
        Edge ed; ed.c = cols[e] * VEC; ed.w = vals[e];
        g_edge[idx] = ed;
    } else {
        int b = blockIdx.x - 1024;
        int m = b * 8 + (t >> 5);
        int n = l >> 2;
        int f0 = 8 * (l & 3);
        const float* xp = &x[((size_t)n * Mv + m) * FINv + f0];
        float4 va = *(const float4*)xp;
        float4 vb = *(const float4*)(xp + 4);
        uint4 u;
        __half2 h;
        h = __floats2half2_rn(va.x, va.y); u.x = *(u32*)&h;
        h = __floats2half2_rn(va.z, va.w); u.y = *(u32*)&h;
        h = __floats2half2_rn(vb.x, vb.y); u.z = *(u32*)&h;
        h = __floats2half2_rn(vb.z, vb.w); u.w = *(u32*)&h;
        *(uint4*)&g_T[0][(size_t)m * VEC + 8 * l] = u;
    }
}

// ---- lane-cooperative gather (kept for k_step_fin) ----
__device__ __forceinline__ void gather_warp(const __half* __restrict__ Tprev,
                                            int s, int deg, int l,
                                            float2& r0, float2& r1, float2& r2, float2& r3) {
    Edge myEd; myEd.c = 0; myEd.w = 0.f;
    if (l < deg) myEd = g_edge[s + l];
    int dmain = min(deg, 32);
    int dpad = (dmain + 3) & ~3;

    float a0x=0.f,a0y=0.f,a1x=0.f,a1y=0.f,a2x=0.f,a2y=0.f,a3x=0.f,a3y=0.f;
    for (int i = 0; i < dpad; i += 4) {
        int   c0 = __shfl_sync(0xffffffffu, myEd.c, i + 0);
        float w0 = __shfl_sync(0xffffffffu, myEd.w, i + 0);
        int   c1 = __shfl_sync(0xffffffffu, myEd.c, i + 1);
        float w1 = __shfl_sync(0xffffffffu, myEd.w, i + 1);
        int   c2 = __shfl_sync(0xffffffffu, myEd.c, i + 2);
        float w2 = __shfl_sync(0xffffffffu, myEd.w, i + 2);
        int   c3 = __shfl_sync(0xffffffffu, myEd.c, i + 3);
        float w3 = __shfl_sync(0xffffffffu, myEd.w, i + 3);
        uint4 v0 = *(const uint4*)&Tprev[(size_t)c0 + 8 * l];
        uint4 v1 = *(const uint4*)&Tprev[(size_t)c1 + 8 * l];
        uint4 v2 = *(const uint4*)&Tprev[(size_t)c2 + 8 * l];
        uint4 v3 = *(const uint4*)&Tprev[(size_t)c3 + 8 * l];
#define ACC(V, W) { \
        float2 q0 = __half22float2(*(__half2*)&V.x); \
        float2 q1 = __half22float2(*(__half2*)&V.y); \
        float2 q2 = __half22float2(*(__half2*)&V.z); \
        float2 q3 = __half22float2(*(__half2*)&V.w); \
        a0x += W * q0.x; a0y += W * q0.y; \
        a1x += W * q1.x; a1y += W * q1.y; \
        a2x += W * q2.x; a2y += W * q2.y; \
        a3x += W * q3.x; a3y += W * q3.y; }
        ACC(v0, w0) ACC(v1, w1) ACC(v2, w2) ACC(v3, w3)
#undef ACC
    }
    for (int i = 32; i < deg; i++) {
        Edge ed = g_edge[s + i];
        uint4 v = *(const uint4*)&Tprev[(size_t)ed.c + 8 * l];
        float wv = ed.w;
        float2 q0 = __half22float2(*(__half2*)&v.x);
        float2 q1 = __half22float2(*(__half2*)&v.y);
        float2 q2 = __half22float2(*(__half2*)&v.z);
        float2 q3 = __half22float2(*(__half2*)&v.w);
        a0x += wv * q0.x; a0y += wv * q0.y;
        a1x += wv * q1.x; a1y += wv * q1.y;
        a2x += wv * q2.x; a2y += wv * q2.y;
        a3x += wv * q3.x; a3y += wv * q3.y;
    }
    r0 = make_float2(a0x, a0y); r1 = make_float2(a1x, a1y);
    r2 = make_float2(a2x, a2y); r3 = make_float2(a3x, a3y);
}

// ---------------- Chebyshev step on tensor cores ----------------
// Block handles rows m0..m0+7; edges form one contiguous CSR slice.
// B-tile [KCAP x 256] fp16 = gathered neighbor vectors; S [16 x KCAP] = edge
// weights (hi+lo fp16 split recovers fp32 weight precision; products exact,
// accumulate fp32). T_k = (2)·S@B − T_{k-2} (scale folded into S).
#define SMEM_SB   0
#define SMEM_SS   (KCAP * B_LD * 2)                       // 50688
#define SMEM_COL  (SMEM_SS + 2 * 16 * S_LD * 2)           // 57344
#define SMEM_RS   (SMEM_COL + KCAP * 4)                   // 57728
#define SMEM_STEP (SMEM_RS + 48)                          // 57776

__global__ void __launch_bounds__(256) k_step(int prevIdx, int ppIdx, int curIdx, int isFirst) {
    extern __shared__ char smem[];
    __half* sB   = (__half*)(smem + SMEM_SB);
    __half* sS0  = (__half*)(smem + SMEM_SS);
    __half* sS1  = sS0 + 16 * S_LD;
    int*    sCol = (int*)(smem + SMEM_COL);
    int*    sRS  = (int*)(smem + SMEM_RS);
    float*  smC  = (float*)sB;                 // alias; used after final sync

    int t = threadIdx.x, w = t >> 5, l = t & 31;
    int m0 = blockIdx.x * 8, m = m0 + w;

    const __half* __restrict__ Tprev = g_T[prevIdx];
    const __half* __restrict__ Tpp   = g_T[ppIdx];
    __half* __restrict__ Tcur        = g_T[curIdx];

    int s, e;
    row_bounds(m, l, s, e);
    if (l == 0) { sRS[w] = s; if (w == 7) sRS[8] = e; }

    uint4 ppu = make_uint4(0, 0, 0, 0);
    if (!isFirst) ppu = *(const uint4*)&Tpp[(size_t)m * VEC + 8 * l];
    __syncthreads();

    int bs = sRS[0], be = sRS[8];

    wmma::fragment<wmma::accumulator, 16, 16, 16, float> acc0, acc1;
    wmma::fill_fragment(acc0, 0.f);
    wmma::fill_fragment(acc1, 0.f);

    for (int cbase = bs; cbase < be; cbase += KCAP) {
        int ccnt = min(KCAP, be - cbase);
        // zero S (hi+lo), as u32
        for (int i = t; i < (2 * 16 * S_LD) / 2; i += 256)
            ((u32*)sS0)[i] = 0;
        __syncthreads();
        // edge read + S scatter (threads < ccnt)
        if (t < ccnt) {
            Edge ed = g_edge[cbase + t];
            sCol[t] = ed.c;
            int gidx = cbase + t;
            int r = 0;
#pragma unroll
            for (int q = 1; q < 8; q++) r += (gidx >= sRS[q]);
            float ws = isFirst ? ed.w : 2.f * ed.w;
            __half hi = __float2half_rn(ws);
            __half lo = __float2half_rn(ws - __half2float(hi));
            sS0[r * S_LD + t] = hi;
            sS1[r * S_LD + t] = lo;
        }
        __syncthreads();
        // stage B rows: warp w handles slots j = i*8 + w (12 independent LDG.128)
#pragma unroll
        for (int i = 0; i < KCAP / 8; i++) {
            int j = i * 8 + w;
            uint4 v = make_uint4(0, 0, 0, 0);
            if (j < ccnt) v = *(const uint4*)&Tprev[(size_t)sCol[j] + 8 * l];
            *(uint4*)&sB[j * B_LD + 8 * l] = v;
        }
        __syncthreads();
        // mma: warp w -> cols [32w, 32w+32), k-tiles over staged edges
        int kts = (ccnt + 15) >> 4;
        for (int kt = 0; kt < kts; kt++) {
            wmma::fragment<wmma::matrix_a, 16, 16, 16, __half, wmma::row_major> fhi, flo;
            wmma::load_matrix_sync(fhi, &sS0[kt * 16], S_LD);
            wmma::load_matrix_sync(flo, &sS1[kt * 16], S_LD);
            wmma::fragment<wmma::matrix_b, 16, 16, 16, __half, wmma::row_major> fb0, fb1;
            wmma::load_matrix_sync(fb0, &sB[kt * 16 * B_LD + w * 32], B_LD);
            wmma::load_matrix_sync(fb1, &sB[kt * 16 * B_LD + w * 32 + 16], B_LD);
            wmma::mma_sync(acc0, fhi, fb0, acc0);
            wmma::mma_sync(acc0, flo, fb0, acc0);
            wmma::mma_sync(acc1, fhi, fb1, acc1);
            wmma::mma_sync(acc1, flo, fb1, acc1);
        }
        __syncthreads();   // mma reads done before next chunk's S zero / B overwrite
    }

    // store acc -> smC [16 x 256] (alias on sB; all mma reads complete)
    wmma::store_matrix_sync(&smC[w * 32], acc0, 256, wmma::mem_row_major);
    wmma::store_matrix_sync(&smC[w * 32 + 16], acc1, 256, wmma::mem_row_major);
    __syncthreads();

    // epilogue: T_k[m, 8l..8l+7] = smC[w][8l..] (- Tpp)
    float4 c0 = *(float4*)&smC[w * 256 + 8 * l];
    float4 c1 = *(float4*)&smC[w * 256 + 8 * l + 4];
    if (!isFirst) {
        float2 p0 = __half22float2(*(__half2*)&ppu.x);
        float2 p1 = __half22float2(*(__half2*)&ppu.y);
        float2 p2 = __half22float2(*(__half2*)&ppu.z);
        float2 p3 = __half22float2(*(__half2*)&ppu.w);
        c0.x -= p0.x; c0.y -= p0.y; c0.z -= p1.x; c0.w -= p1.y;
        c1.x -= p2.x; c1.y -= p2.y; c1.z -= p3.x; c1.w -= p3.y;
    }
    uint4 u;
    __half2 h;
    h = __floats2half2_rn(c0.x, c0.y); u.x = *(u32*)&h;
    h = __floats2half2_rn(c0.z, c0.w); u.y = *(u32*)&h;
    h = __floats2half2_rn(c1.x, c1.y); u.z = *(u32*)&h;
    h = __floats2half2_rn(c1.z, c1.w); u.w = *(u32*)&h;
    *(uint4*)&Tcur[(size_t)m * VEC + 8 * l] = u;
}

// ---------------- fused last step + tensor-core GEMM (R13 version) ----------------
#define A_LD 168   // 160 + 8 halfs pad

__global__ void __launch_bounds__(256) k_step_fin(const float* __restrict__ bias,
                                                  float* __restrict__ out) {
    __shared__ alignas(16) char smBuf[64 * A_LD * 2];     // smA / smC alias
    __shared__ alignas(16) __half smB[160 * FILTv];
    __shared__ float smBias[16 * FILTv];
    __half* smA = (__half*)smBuf;
    float*  smC = (float*)smBuf;

    int t = threadIdx.x;
    int w = t >> 5, l = t & 31;
    int m0 = blockIdx.x * 8;
    int m = m0 + w;
    int n = l >> 2, f0 = 8 * (l & 3);
    int tr = n * 8 + w;

#pragma unroll
    for (int kr = 0; kr < 4; kr++) {
        uint4 v = *(const uint4*)&g_T[kr][(size_t)m * VEC + 8 * l];
        *(uint4*)&smA[tr * A_LD + kr * 32 + f0] = v;
    }

    for (int i = t; i < 640; i += 256)
        ((uint4*)smB)[i] = ((const uint4*)g_W)[i];
    for (int i = t; i < 16 * FILTv; i += 256)
        smBias[i] = bias[i & 31];

    {
        uint4 ppu = *(const uint4*)&g_T[2][(size_t)m * VEC + 8 * l];
        int s, e;
        row_bounds(m, l, s, e);
        float2 a0, a1, a2, a3;
        gather_warp(g_T[3], s, e - s, l, a0, a1, a2, a3);
        float2 p0 = __half22float2(*(__half2*)&ppu.x);
        float2 p1 = __half22float2(*(__half2*)&ppu.y);
        float2 p2 = __half22float2(*(__half2*)&ppu.z);
        float2 p3 = __half22float2(*(__half2*)&ppu.w);
        uint4 u;
        __half2 h;
        h = __floats2half2_rn(2.f*a0.x - p0.x, 2.f*a0.y - p0.y); u.x = *(u32*)&h;
        h = __floats2half2_rn(2.f*a1.x - p1.x, 2.f*a1.y - p1.y); u.y = *(u32*)&h;
        h = __floats2half2_rn(2.f*a2.x - p2.x, 2.f*a2.y - p2.y); u.z = *(u32*)&h;
        h = __floats2half2_rn(2.f*a3.x - p3.x, 2.f*a3.y - p3.y); u.w = *(u32*)&h;
        *(uint4*)&smA[tr * A_LD + 4 * 32 + f0] = u;
    }
    __syncthreads();

    {
        int wr = w >> 1, wc = w & 1;
        wmma::fragment<wmma::accumulator, 16, 16, 16, float> acc;
        wmma::load_matrix_sync(acc, smBias + wc * 16, FILTv, wmma::mem_row_major);
#pragma unroll
        for (int kk = 0; kk < 10; kk++) {
            wmma::fragment<wmma::matrix_a, 16, 16, 16, __half, wmma::row_major> fa;
            wmma::fragment<wmma::matrix_b, 16, 16, 16, __half, wmma::row_major> fb;
            wmma::load_matrix_sync(fa, &smA[16 * wr * A_LD + kk * 16], A_LD);
            wmma::load_matrix_sync(fb, &smB[kk * 16 * FILTv + wc * 16], FILTv);
            wmma::mma_sync(acc, fa, fb, acc);
        }
        __syncthreads();
        wmma::store_matrix_sync(&smC[16 * wr * FILTv + wc * 16], acc, FILTv, wmma::mem_row_major);
    }
    __syncthreads();

    for (int i = t; i < 64 * FILTv; i += 256) {
        int rr = i >> 5, filt = i & 31;
        int nn = rr >> 3, ml = rr & 7;
        out[((size_t)nn * Mv + m0 + ml) * FILTv + filt] = smC[i];
    }
}

extern "C" void kernel_launch(void* const* d_in, const int* in_sizes, int n_in,
                              void* d_out, int out_size) {
    const float* x    = (const float*)d_in[0];
    const float* vals = (const float*)d_in[1];
    const float* kern = (const float*)d_in[2];
    const float* bias = (const float*)d_in[3];
    const int*   rows = (const int*)  d_in[4];
    const int*   cols = (const int*)  d_in[5];
    float* out = (float*)d_out;

    cudaFuncSetAttribute(k_step, cudaFuncAttributeMaxDynamicSharedMemorySize, SMEM_STEP);

    k_hist        <<<Ev / 256, 256>>>(rows);                     // 1
    k_scan1       <<<33, 1024>>>(kern);                          // 2
    k_scatter_init<<<1024 + Mv / 8, 256>>>(rows, cols, vals, x); // 3
    k_step<<<Mv / 8, 256, SMEM_STEP>>>(0, 0, 1, 1);   // 4  T1 = L T0
    k_step<<<Mv / 8, 256, SMEM_STEP>>>(1, 0, 2, 0);   // 5  T2
    k_step<<<Mv / 8, 256, SMEM_STEP>>>(2, 1, 3, 0);   // 6  T3  <- profiled slot
    k_step_fin<<<Mv / 8, 256>>>(bias, out);           // 7  T4 + GEMM + out
}

// round 15
// speedup vs baseline: 1.7149x; 1.7149x over previous
#include <cuda_runtime.h>
#include <cuda_fp16.h>
#include <mma.h>

using namespace nvcuda;

#define Mv    32768
#define Ev    262144
#define RANKv 5
#define FILTv 32
#define FINv  32
#define NBv   8
#define VEC   256   // FIN * NB

typedef unsigned long long u64;
typedef unsigned int u32;

struct alignas(8) Edge { int c; float w; };

__device__ __half g_T[4][(size_t)Mv * VEC];
__device__ int    g_cnt[Mv];         // zero at module load; re-zeroed by k_scan1 each replay
__device__ int    g_rowptr[Mv];      // block-local exclusive scans
__device__ int    g_bsum[32];        // per-1024-chunk totals
__device__ int    g_pos[Ev];
__device__ Edge   g_edge[Ev];
__device__ __half g_W[160 * FILTv];  // W fp16, rows = kr*32+f

// ---- packed f32x2 helpers ----
__device__ __forceinline__ u64 f2_pack(float lo, float hi) {
    u64 d; asm("mov.b64 %0, {%1, %2};" : "=l"(d) : "f"(lo), "f"(hi)); return d;
}
__device__ __forceinline__ void f2_unpack(u64 v, float& lo, float& hi) {
    asm("mov.b64 {%0, %1}, %2;" : "=f"(lo), "=f"(hi) : "l"(v));
}
__device__ __forceinline__ u64 f2_fma(u64 a, u64 b, u64 c) {
    u64 d; asm("fma.rn.f32x2 %0, %1, %2, %3;" : "=l"(d) : "l"(a), "l"(b), "l"(c)); return d;
}
__device__ __forceinline__ u64 h2u64(u32 h) {
    float2 f = __half22float2(*(__half2*)&h);
    return f2_pack(f.x, f.y);
}

// warp-wide exclusive scan of g_bsum; base offset for chunk j (per-lane j ok)
__device__ __forceinline__ int chunk_base(int l, int j) {
    int own = g_bsum[l];
    int v = own;
#pragma unroll
    for (int off = 1; off < 32; off <<= 1) {
        int u = __shfl_up_sync(0xffffffffu, v, off);
        if (l >= off) v += u;
    }
    int excl = v - own;
    return __shfl_sync(0xffffffffu, excl, j & 31);
}

// row [start,end) bounds for row m, lane l (full-warp collective)
__device__ __forceinline__ void row_bounds(int m, int l, int& s, int& e) {
    int own = g_bsum[l];
    int v = own;
#pragma unroll
    for (int off = 1; off < 32; off <<= 1) {
        int u = __shfl_up_sync(0xffffffffu, v, off);
        if (l >= off) v += u;
    }
    int excl = v - own;
    s = __shfl_sync(0xffffffffu, excl, m >> 10) + g_rowptr[m];
    e = (m == Mv - 1) ? Ev
        : __shfl_sync(0xffffffffu, excl, ((m + 1) >> 10) & 31) + g_rowptr[m + 1];
}

// ---------------- CSR build ----------------
// fused: blocks [0,1024) histogram; blocks [1024,5120) transpose x -> T0 fp16
__global__ void __launch_bounds__(256) k_hist(const int* __restrict__ rows,
                                              const float* __restrict__ x) {
    int t = threadIdx.x;
    if (blockIdx.x < 1024) {
        int e = blockIdx.x * 256 + t;
        g_pos[e] = atomicAdd(&g_cnt[rows[e]], 1);
    } else {
        int b = blockIdx.x - 1024;
        int l = t & 31;
        int m = b * 8 + (t >> 5);
        int n = l >> 2;
        int f0 = 8 * (l & 3);
        const float* xp = &x[((size_t)n * Mv + m) * FINv + f0];
        float4 va = *(const float4*)xp;
        float4 vb = *(const float4*)(xp + 4);
        uint4 u;
        __half2 h;
        h = __floats2half2_rn(va.x, va.y); u.x = *(u32*)&h;
        h = __floats2half2_rn(va.z, va.w); u.y = *(u32*)&h;
        h = __floats2half2_rn(vb.x, vb.y); u.z = *(u32*)&h;
        h = __floats2half2_rn(vb.z, vb.w); u.w = *(u32*)&h;
        *(uint4*)&g_T[0][(size_t)m * VEC + 8 * l] = u;
    }
}

// grid 33: blocks 0..31 scan 1024-chunks of g_cnt (and re-zero); block 32 converts W
__global__ void k_scan1(const float* __restrict__ kern) {
    if (blockIdx.x == 32) {
        int t = threadIdx.x;
        for (int i = t; i < 160 * FILTv; i += 1024) {
            int row = i >> 5, filt = i & 31;
            int kr = row >> 5, f = row & 31;
            g_W[i] = __float2half_rn(kern[(f * RANKv + kr) * FILTv + filt]);
        }
        return;
    }
    __shared__ int sh[1024];
    int t = threadIdx.x;
    int i = blockIdx.x * 1024 + t;
    int c = g_cnt[i];
    g_cnt[i] = 0;
    sh[t] = c;
    __syncthreads();
#pragma unroll
    for (int off = 1; off < 1024; off <<= 1) {
        int v = (t >= off) ? sh[t - off] : 0;
        __syncthreads();
        sh[t] += v;
        __syncthreads();
    }
    g_rowptr[i] = sh[t] - c;
    if (t == 1023) g_bsum[blockIdx.x] = sh[t];
}

__global__ void __launch_bounds__(256) k_scatter(const int* __restrict__ rows,
                                                 const int* __restrict__ cols,
                                                 const float* __restrict__ vals) {
    int t = threadIdx.x;
    int l = t & 31;
    int e = blockIdx.x * 256 + t;
    int r = rows[e];
    int base = chunk_base(l, r >> 10);
    int idx = base + g_rowptr[r] + g_pos[e];
    Edge ed; ed.c = cols[e] * VEC; ed.w = vals[e];
    g_edge[idx] = ed;
}

// ---- lane-cooperative gather, packed f32x2 accumulate ----
__device__ __forceinline__ void gather_warp(const __half* __restrict__ Tprev,
                                            int s, int deg, int l,
                                            u64& A0, u64& A1, u64& A2, u64& A3) {
    Edge myEd; myEd.c = 0; myEd.w = 0.f;
    if (l < deg) myEd = g_edge[s + l];       // one coalesced 256B warp load
    int dmain = min(deg, 32);
    int dpad = (dmain + 3) & ~3;             // zero-weight padding to x4

    A0 = 0; A1 = 0; A2 = 0; A3 = 0;
    for (int i = 0; i < dpad; i += 4) {
        int   c0 = __shfl_sync(0xffffffffu, myEd.c, i + 0);
        float w0 = __shfl_sync(0xffffffffu, myEd.w, i + 0);
        int   c1 = __shfl_sync(0xffffffffu, myEd.c, i + 1);
        float w1 = __shfl_sync(0xffffffffu, myEd.w, i + 1);
        int   c2 = __shfl_sync(0xffffffffu, myEd.c, i + 2);
        float w2 = __shfl_sync(0xffffffffu, myEd.w, i + 2);
        int   c3 = __shfl_sync(0xffffffffu, myEd.c, i + 3);
        float w3 = __shfl_sync(0xffffffffu, myEd.w, i + 3);
        uint4 v0 = *(const uint4*)&Tprev[(size_t)c0 + 8 * l];
        uint4 v1 = *(const uint4*)&Tprev[(size_t)c1 + 8 * l];
        uint4 v2 = *(const uint4*)&Tprev[(size_t)c2 + 8 * l];
        uint4 v3 = *(const uint4*)&Tprev[(size_t)c3 + 8 * l];
        u64 p0 = f2_pack(w0, w0), p1 = f2_pack(w1, w1);
        u64 p2 = f2_pack(w2, w2), p3 = f2_pack(w3, w3);
        A0 = f2_fma(p0, h2u64(v0.x), A0);
        A1 = f2_fma(p0, h2u64(v0.y), A1);
        A2 = f2_fma(p0, h2u64(v0.z), A2);
        A3 = f2_fma(p0, h2u64(v0.w), A3);
        A0 = f2_fma(p1, h2u64(v1.x), A0);
        A1 = f2_fma(p1, h2u64(v1.y), A1);
        A2 = f2_fma(p1, h2u64(v1.z), A2);
        A3 = f2_fma(p1, h2u64(v1.w), A3);
        A0 = f2_fma(p2, h2u64(v2.x), A0);
        A1 = f2_fma(p2, h2u64(v2.y), A1);
        A2 = f2_fma(p2, h2u64(v2.z), A2);
        A3 = f2_fma(p2, h2u64(v2.w), A3);
        A0 = f2_fma(p3, h2u64(v3.x), A0);
        A1 = f2_fma(p3, h2u64(v3.y), A1);
        A2 = f2_fma(p3, h2u64(v3.z), A2);
        A3 = f2_fma(p3, h2u64(v3.w), A3);
    }
    // fallback for degree > 32 (practically never with E/M = 8)
    for (int i = 32; i < deg; i++) {
        Edge ed = g_edge[s + i];
        uint4 v = *(const uint4*)&Tprev[(size_t)ed.c + 8 * l];
        u64 p = f2_pack(ed.w, ed.w);
        A0 = f2_fma(p, h2u64(v.x), A0);
        A1 = f2_fma(p, h2u64(v.y), A1);
        A2 = f2_fma(p, h2u64(v.z), A2);
        A3 = f2_fma(p, h2u64(v.w), A3);
    }
}

// ---------------- Chebyshev step: one warp per row, fp16 in/out, fp32 accum ----------------
__global__ void __launch_bounds__(256) k_step(int prevIdx, int ppIdx, int curIdx, int isFirst) {
    int t = threadIdx.x;
    int w = t >> 5, l = t & 31;
    int m = blockIdx.x * 8 + w;

    const __half* __restrict__ Tprev = g_T[prevIdx];
    const __half* __restrict__ Tpp   = g_T[ppIdx];
    __half* __restrict__ Tcur        = g_T[curIdx];

    size_t base = (size_t)m * VEC + 8 * l;
    uint4 ppu = make_uint4(0, 0, 0, 0);
    if (!isFirst) ppu = *(const uint4*)&Tpp[base];

    int s, e;
    row_bounds(m, l, s, e);

    u64 A0, A1, A2, A3;
    gather_warp(Tprev, s, e - s, l, A0, A1, A2, A3);

    float a0x, a0y, a1x, a1y, a2x, a2y, a3x, a3y;
    f2_unpack(A0, a0x, a0y); f2_unpack(A1, a1x, a1y);
    f2_unpack(A2, a2x, a2y); f2_unpack(A3, a3x, a3y);
    if (!isFirst) {
        float2 p0 = __half22float2(*(__half2*)&ppu.x);
        float2 p1 = __half22float2(*(__half2*)&ppu.y);
        float2 p2 = __half22float2(*(__half2*)&ppu.z);
        float2 p3 = __half22float2(*(__half2*)&ppu.w);
        a0x = 2.f * a0x - p0.x;  a0y = 2.f * a0y - p0.y;
        a1x = 2.f * a1x - p1.x;  a1y = 2.f * a1y - p1.y;
        a2x = 2.f * a2x - p2.x;  a2y = 2.f * a2y - p2.y;
        a3x = 2.f * a3x - p3.x;  a3y = 2.f * a3y - p3.y;
    }

    uint4 u;
    __half2 h;
    h = __floats2half2_rn(a0x, a0y); u.x = *(u32*)&h;
    h = __floats2half2_rn(a1x, a1y); u.y = *(u32*)&h;
    h = __floats2half2_rn(a2x, a2y); u.z = *(u32*)&h;
    h = __floats2half2_rn(a3x, a3y); u.w = *(u32*)&h;
    *(uint4*)&Tcur[base] = u;
}

// ---------------- fused last step + tensor-core GEMM ----------------
#define A_LD 168   // 160 + 8 halfs pad

__global__ void __launch_bounds__(256) k_step_fin(const float* __restrict__ bias,
                                                  float* __restrict__ out) {
    __shared__ alignas(16) char smBuf[64 * A_LD * 2];     // smA (21504 B) / smC (8192 B) alias
    __shared__ alignas(16) __half smB[160 * FILTv];       // 10240 B
    __shared__ float smBias[16 * FILTv];                  //  2048 B
    __half* smA = (__half*)smBuf;
    float*  smC = (float*)smBuf;

    int t = threadIdx.x;
    int w = t >> 5, l = t & 31;
    int m0 = blockIdx.x * 8;
    int m = m0 + w;
    int n = l >> 2, f0 = 8 * (l & 3);
    int tr = n * 8 + w;

    // stage T0..T3 rows of A
#pragma unroll
    for (int kr = 0; kr < 4; kr++) {
        uint4 v = *(const uint4*)&g_T[kr][(size_t)m * VEC + 8 * l];
        *(uint4*)&smA[tr * A_LD + kr * 32 + f0] = v;
    }

    // B: bulk-copy pre-converted fp16 W; bias rows
    for (int i = t; i < 640; i += 256)
        ((uint4*)smB)[i] = ((const uint4*)g_W)[i];
    for (int i = t; i < 16 * FILTv; i += 256)
        smBias[i] = bias[i & 31];

    // gather T4 = 2 L T3 - T2 for row m
    {
        uint4 ppu = *(const uint4*)&g_T[2][(size_t)m * VEC + 8 * l];
        int s, e;
        row_bounds(m, l, s, e);
        u64 A0, A1, A2, A3;
        gather_warp(g_T[3], s, e - s, l, A0, A1, A2, A3);
        float a0x, a0y, a1x, a1y, a2x, a2y, a3x, a3y;
        f2_unpack(A0, a0x, a0y); f2_unpack(A1, a1x, a1y);
        f2_unpack(A2, a2x, a2y); f2_unpack(A3, a3x, a3y);
        float2 p0 = __half22float2(*(__half2*)&ppu.x);
        float2 p1 = __half22float2(*(__half2*)&ppu.y);
        float2 p2 = __half22float2(*(__half2*)&ppu.z);
        float2 p3 = __half22float2(*(__half2*)&ppu.w);
        uint4 u;
        __half2 h;
        h = __floats2half2_rn(2.f*a0x - p0.x, 2.f*a0y - p0.y); u.x = *(u32*)&h;
        h = __floats2half2_rn(2.f*a1x - p1.x, 2.f*a1y - p1.y); u.y = *(u32*)&h;
        h = __floats2half2_rn(2.f*a2x - p2.x, 2.f*a2y - p2.y); u.z = *(u32*)&h;
        h = __floats2half2_rn(2.f*a3x - p3.x, 2.f*a3y - p3.y); u.w = *(u32*)&h;
        *(uint4*)&smA[tr * A_LD + 4 * 32 + f0] = u;
    }
    __syncthreads();

    // wmma: 8 warps -> 8 tiles (row-tile w>>1, col-tile w&1), acc init = bias
    {
        int wr = w >> 1, wc = w & 1;
        wmma::fragment<wmma::accumulator, 16, 16, 16, float> acc;
        wmma::load_matrix_sync(acc, smBias + wc * 16, FILTv, wmma::mem_row_major);
#pragma unroll
        for (int kk = 0; kk < 10; kk++) {
            wmma::fragment<wmma::matrix_a, 16, 16, 16, __half, wmma::row_major> fa;
            wmma::fragment<wmma::matrix_b, 16, 16, 16, __half, wmma::row_major> fb;
            wmma::load_matrix_sync(fa, &smA[16 * wr * A_LD + kk * 16], A_LD);
            wmma::load_matrix_sync(fb, &smB[kk * 16 * FILTv + wc * 16], FILTv);
            wmma::mma_sync(acc, fa, fb, acc);
        }
        __syncthreads();   // all smA reads done before smC overwrites the alias
        wmma::store_matrix_sync(&smC[16 * wr * FILTv + wc * 16], acc, FILTv, wmma::mem_row_major);
    }
    __syncthreads();

    // scatter to out: rows tr = n*8+m_local
    for (int i = t; i < 64 * FILTv; i += 256) {
        int rr = i >> 5, filt = i & 31;
        int nn = rr >> 3, ml = rr & 7;
        out[((size_t)nn * Mv + m0 + ml) * FILTv + filt] = smC[i];
    }
}

extern "C" void kernel_launch(void* const* d_in, const int* in_sizes, int n_in,
                              void* d_out, int out_size) {
    const float* x    = (const float*)d_in[0];
    const float* vals = (const float*)d_in[1];
    const float* kern = (const float*)d_in[2];
    const float* bias = (const float*)d_in[3];
    const int*   rows = (const int*)  d_in[4];
    const int*   cols = (const int*)  d_in[5];
    float* out = (float*)d_out;

    k_hist   <<<1024 + Mv / 8, 256>>>(rows, x);       // 1  hist + x->T0 transpose
    k_scan1  <<<33, 1024>>>(kern);                    // 2  parallel scan + W conv
    k_scatter<<<Ev / 256, 256>>>(rows, cols, vals);   // 3
    k_step<<<Mv / 8, 256>>>(0, 0, 1, 1);   // 4  T1 = L T0
    k_step<<<Mv / 8, 256>>>(1, 0, 2, 0);   // 5  T2
    k_step<<<Mv / 8, 256>>>(2, 1, 3, 0);   // 6  T3  <- profiled slot
    k_step_fin<<<Mv / 8, 256>>>(bias, out);  // 7  T4 + GEMM + out
}

// round 16
// speedup vs baseline: 1.7590x; 1.0257x over previous
#include <cuda_runtime.h>
#include <cuda_fp16.h>
#include <mma.h>

using namespace nvcuda;

#define Mv    32768
#define Ev    262144
#define RANKv 5
#define FILTv 32
#define FINv  32
#define NBv   8
#define VEC   256   // FIN * NB

typedef unsigned long long u64;
typedef unsigned int u32;

struct alignas(8) Edge { int c; float w; };

__device__ __half g_T[4][(size_t)Mv * VEC];
__device__ int    g_cnt[Mv];         // zero at module load; re-zeroed by k_scan1 each replay
__device__ int    g_rowptr[Mv];      // block-local exclusive scans
__device__ int    g_bsum[32];        // per-1024-chunk totals
__device__ int    g_pos[Ev];
__device__ Edge   g_edge[Ev];
__device__ __half g_W[160 * FILTv];  // W fp16, rows = kr*32+f

// warp-wide exclusive scan of g_bsum; base offset for chunk j (per-lane j ok)
__device__ __forceinline__ int chunk_base(int l, int j) {
    int own = g_bsum[l];
    int v = own;
#pragma unroll
    for (int off = 1; off < 32; off <<= 1) {
        int u = __shfl_up_sync(0xffffffffu, v, off);
        if (l >= off) v += u;
    }
    int excl = v - own;
    return __shfl_sync(0xffffffffu, excl, j & 31);
}

// row [start,end) bounds for row m, lane l (full-warp collective)
__device__ __forceinline__ void row_bounds(int m, int l, int& s, int& e) {
    int own = g_bsum[l];
    int v = own;
#pragma unroll
    for (int off = 1; off < 32; off <<= 1) {
        int u = __shfl_up_sync(0xffffffffu, v, off);
        if (l >= off) v += u;
    }
    int excl = v - own;
    s = __shfl_sync(0xffffffffu, excl, m >> 10) + g_rowptr[m];
    e = (m == Mv - 1) ? Ev
        : __shfl_sync(0xffffffffu, excl, ((m + 1) >> 10) & 31) + g_rowptr[m + 1];
}

// ---------------- CSR build ----------------
// fused: blocks [0,1024) histogram; blocks [1024,5120) transpose x -> T0 fp16
__global__ void __launch_bounds__(256) k_hist(const int* __restrict__ rows,
                                              const float* __restrict__ x) {
    int t = threadIdx.x;
    if (blockIdx.x < 1024) {
        int e = blockIdx.x * 256 + t;
        g_pos[e] = atomicAdd(&g_cnt[rows[e]], 1);
    } else {
        int b = blockIdx.x - 1024;
        int l = t & 31;
        int m = b * 8 + (t >> 5);
        int n = l >> 2;
        int f0 = 8 * (l & 3);
        const float* xp = &x[((size_t)n * Mv + m) * FINv + f0];
        float4 va = *(const float4*)xp;
        float4 vb = *(const float4*)(xp + 4);
        uint4 u;
        __half2 h;
        h = __floats2half2_rn(va.x, va.y); u.x = *(u32*)&h;
        h = __floats2half2_rn(va.z, va.w); u.y = *(u32*)&h;
        h = __floats2half2_rn(vb.x, vb.y); u.z = *(u32*)&h;
        h = __floats2half2_rn(vb.z, vb.w); u.w = *(u32*)&h;
        *(uint4*)&g_T[0][(size_t)m * VEC + 8 * l] = u;
    }
}

// grid 33: blocks 0..31 scan 1024-chunks of g_cnt (and re-zero); block 32 converts W
__global__ void k_scan1(const float* __restrict__ kern) {
    if (blockIdx.x == 32) {
        int t = threadIdx.x;
        for (int i = t; i < 160 * FILTv; i += 1024) {
            int row = i >> 5, filt = i & 31;
            int kr = row >> 5, f = row & 31;
            g_W[i] = __float2half_rn(kern[(f * RANKv + kr) * FILTv + filt]);
        }
        return;
    }
    __shared__ int sh[1024];
    int t = threadIdx.x;
    int i = blockIdx.x * 1024 + t;
    int c = g_cnt[i];
    g_cnt[i] = 0;
    sh[t] = c;
    __syncthreads();
#pragma unroll
    for (int off = 1; off < 1024; off <<= 1) {
        int v = (t >= off) ? sh[t - off] : 0;
        __syncthreads();
        sh[t] += v;
        __syncthreads();
    }
    g_rowptr[i] = sh[t] - c;
    if (t == 1023) g_bsum[blockIdx.x] = sh[t];
}

__global__ void __launch_bounds__(256) k_scatter(const int* __restrict__ rows,
                                                 const int* __restrict__ cols,
                                                 const float* __restrict__ vals) {
    int t = threadIdx.x;
    int l = t & 31;
    int e = blockIdx.x * 256 + t;
    int r = rows[e];
    int base = chunk_base(l, r >> 10);
    int idx = base + g_rowptr[r] + g_pos[e];
    Edge ed; ed.c = cols[e] * VEC; ed.w = vals[e];
    g_edge[idx] = ed;
}

// ---- lane-cooperative gather (R13 scalar accumulate: the proven optimum) ----
__device__ __forceinline__ void gather_warp(const __half* __restrict__ Tprev,
                                            int s, int deg, int l,
                                            float2& r0, float2& r1, float2& r2, float2& r3) {
    Edge myEd; myEd.c = 0; myEd.w = 0.f;
    if (l < deg) myEd = g_edge[s + l];       // one coalesced 256B warp load
    int dmain = min(deg, 32);
    int dpad = (dmain + 3) & ~3;             // zero-weight padding to x4

    float a0x=0.f,a0y=0.f,a1x=0.f,a1y=0.f,a2x=0.f,a2y=0.f,a3x=0.f,a3y=0.f;
    for (int i = 0; i < dpad; i += 4) {
        int   c0 = __shfl_sync(0xffffffffu, myEd.c, i + 0);
        float w0 = __shfl_sync(0xffffffffu, myEd.w, i + 0);
        int   c1 = __shfl_sync(0xffffffffu, myEd.c, i + 1);
        float w1 = __shfl_sync(0xffffffffu, myEd.w, i + 1);
        int   c2 = __shfl_sync(0xffffffffu, myEd.c, i + 2);
        float w2 = __shfl_sync(0xffffffffu, myEd.w, i + 2);
        int   c3 = __shfl_sync(0xffffffffu, myEd.c, i + 3);
        float w3 = __shfl_sync(0xffffffffu, myEd.w, i + 3);
        uint4 v0 = *(const uint4*)&Tprev[(size_t)c0 + 8 * l];
        uint4 v1 = *(const uint4*)&Tprev[(size_t)c1 + 8 * l];
        uint4 v2 = *(const uint4*)&Tprev[(size_t)c2 + 8 * l];
        uint4 v3 = *(const uint4*)&Tprev[(size_t)c3 + 8 * l];
#define ACC(V, W) { \
        float2 q0 = __half22float2(*(__half2*)&V.x); \
        float2 q1 = __half22float2(*(__half2*)&V.y); \
        float2 q2 = __half22float2(*(__half2*)&V.z); \
        float2 q3 = __half22float2(*(__half2*)&V.w); \
        a0x += W * q0.x; a0y += W * q0.y; \
        a1x += W * q1.x; a1y += W * q1.y; \
        a2x += W * q2.x; a2y += W * q2.y; \
        a3x += W * q3.x; a3y += W * q3.y; }
        ACC(v0, w0) ACC(v1, w1) ACC(v2, w2) ACC(v3, w3)
#undef ACC
    }
    // fallback for degree > 32 (practically never with E/M = 8)
    for (int i = 32; i < deg; i++) {
        Edge ed = g_edge[s + i];
        uint4 v = *(const uint4*)&Tprev[(size_t)ed.c + 8 * l];
        float wv = ed.w;
        float2 q0 = __half22float2(*(__half2*)&v.x);
        float2 q1 = __half22float2(*(__half2*)&v.y);
        float2 q2 = __half22float2(*(__half2*)&v.z);
        float2 q3 = __half22float2(*(__half2*)&v.w);
        a0x += wv * q0.x; a0y += wv * q0.y;
        a1x += wv * q1.x; a1y += wv * q1.y;
        a2x += wv * q2.x; a2y += wv * q2.y;
        a3x += wv * q3.x; a3y += wv * q3.y;
    }
    r0 = make_float2(a0x, a0y); r1 = make_float2(a1x, a1y);
    r2 = make_float2(a2x, a2y); r3 = make_float2(a3x, a3y);
}

// ---------------- Chebyshev step: one warp per row, fp16 in/out, fp32 accum ----------------
__global__ void __launch_bounds__(256) k_step(int prevIdx, int ppIdx, int curIdx, int isFirst) {
    int t = threadIdx.x;
    int w = t >> 5, l = t & 31;
    int m = blockIdx.x * 8 + w;

    const __half* __restrict__ Tprev = g_T[prevIdx];
    const __half* __restrict__ Tpp   = g_T[ppIdx];
    __half* __restrict__ Tcur        = g_T[curIdx];

    size_t base = (size_t)m * VEC + 8 * l;
    uint4 ppu = make_uint4(0, 0, 0, 0);
    if (!isFirst) ppu = *(const uint4*)&Tpp[base];

    int s, e;
    row_bounds(m, l, s, e);

    float2 a0, a1, a2, a3;
    gather_warp(Tprev, s, e - s, l, a0, a1, a2, a3);

    if (!isFirst) {
        float2 p0 = __half22float2(*(__half2*)&ppu.x);
        float2 p1 = __half22float2(*(__half2*)&ppu.y);
        float2 p2 = __half22float2(*(__half2*)&ppu.z);
        float2 p3 = __half22float2(*(__half2*)&ppu.w);
        a0.x = 2.f * a0.x - p0.x;  a0.y = 2.f * a0.y - p0.y;
        a1.x = 2.f * a1.x - p1.x;  a1.y = 2.f * a1.y - p1.y;
        a2.x = 2.f * a2.x - p2.x;  a2.y = 2.f * a2.y - p2.y;
        a3.x = 2.f * a3.x - p3.x;  a3.y = 2.f * a3.y - p3.y;
    }

    uint4 u;
    __half2 h;
    h = __floats2half2_rn(a0.x, a0.y); u.x = *(u32*)&h;
    h = __floats2half2_rn(a1.x, a1.y); u.y = *(u32*)&h;
    h = __floats2half2_rn(a2.x, a2.y); u.z = *(u32*)&h;
    h = __floats2half2_rn(a3.x, a3.y); u.w = *(u32*)&h;
    *(uint4*)&Tcur[base] = u;
}

// ---------------- fused last step + tensor-core GEMM ----------------
#define A_LD 168   // 160 + 8 halfs pad

__global__ void __launch_bounds__(256) k_step_fin(const float* __restrict__ bias,
                                                  float* __restrict__ out) {
    __shared__ alignas(16) char smBuf[64 * A_LD * 2];     // smA (21504 B) / smC (8192 B) alias
    __shared__ alignas(16) __half smB[160 * FILTv];       // 10240 B
    __shared__ float smBias[16 * FILTv];                  //  2048 B
    __half* smA = (__half*)smBuf;
    float*  smC = (float*)smBuf;

    int t = threadIdx.x;
    int w = t >> 5, l = t & 31;
    int m0 = blockIdx.x * 8;
    int m = m0 + w;
    int n = l >> 2, f0 = 8 * (l & 3);
    int tr = n * 8 + w;

    // stage T0..T3 rows of A
#pragma unroll
    for (int kr = 0; kr < 4; kr++) {
        uint4 v = *(const uint4*)&g_T[kr][(size_t)m * VEC + 8 * l];
        *(uint4*)&smA[tr * A_LD + kr * 32 + f0] = v;
    }

    // B: bulk-copy pre-converted fp16 W; bias rows
    for (int i = t; i < 640; i += 256)
        ((uint4*)smB)[i] = ((const uint4*)g_W)[i];
    for (int i = t; i < 16 * FILTv; i += 256)
        smBias[i] = bias[i & 31];

    // gather T4 = 2 L T3 - T2 for row m
    {
        uint4 ppu = *(const uint4*)&g_T[2][(size_t)m * VEC + 8 * l];
        int s, e;
        row_bounds(m, l, s, e);
        float2 a0, a1, a2, a3;
        gather_warp(g_T[3], s, e - s, l, a0, a1, a2, a3);
        float2 p0 = __half22float2(*(__half2*)&ppu.x);
        float2 p1 = __half22float2(*(__half2*)&ppu.y);
        float2 p2 = __half22float2(*(__half2*)&ppu.z);
        float2 p3 = __half22float2(*(__half2*)&ppu.w);
        uint4 u;
        __half2 h;
        h = __floats2half2_rn(2.f*a0.x - p0.x, 2.f*a0.y - p0.y); u.x = *(u32*)&h;
        h = __floats2half2_rn(2.f*a1.x - p1.x, 2.f*a1.y - p1.y); u.y = *(u32*)&h;
        h = __floats2half2_rn(2.f*a2.x - p2.x, 2.f*a2.y - p2.y); u.z = *(u32*)&h;
        h = __floats2half2_rn(2.f*a3.x - p3.x, 2.f*a3.y - p3.y); u.w = *(u32*)&h;
        *(uint4*)&smA[tr * A_LD + 4 * 32 + f0] = u;
    }
    __syncthreads();

    // wmma: 8 warps -> 8 tiles (row-tile w>>1, col-tile w&1), acc init = bias
    {
        int wr = w >> 1, wc = w & 1;
        wmma::fragment<wmma::accumulator, 16, 16, 16, float> acc;
        wmma::load_matrix_sync(acc, smBias + wc * 16, FILTv, wmma::mem_row_major);
#pragma unroll
        for (int kk = 0; kk < 10; kk++) {
            wmma::fragment<wmma::matrix_a, 16, 16, 16, __half, wmma::row_major> fa;
            wmma::fragment<wmma::matrix_b, 16, 16, 16, __half, wmma::row_major> fb;
            wmma::load_matrix_sync(fa, &smA[16 * wr * A_LD + kk * 16], A_LD);
            wmma::load_matrix_sync(fb, &smB[kk * 16 * FILTv + wc * 16], FILTv);
            wmma::mma_sync(acc, fa, fb, acc);
        }
        __syncthreads();   // all smA reads done before smC overwrites the alias
        wmma::store_matrix_sync(&smC[16 * wr * FILTv + wc * 16], acc, FILTv, wmma::mem_row_major);
    }
    __syncthreads();

    // scatter to out: rows tr = n*8+m_local
    for (int i = t; i < 64 * FILTv; i += 256) {
        int rr = i >> 5, filt = i & 31;
        int nn = rr >> 3, ml = rr & 7;
        out[((size_t)nn * Mv + m0 + ml) * FILTv + filt] = smC[i];
    }
}

extern "C" void kernel_launch(void* const* d_in, const int* in_sizes, int n_in,
                              void* d_out, int out_size) {
    const float* x    = (const float*)d_in[0];
    const float* vals = (const float*)d_in[1];
    const float* kern = (const float*)d_in[2];
    const float* bias = (const float*)d_in[3];
    const int*   rows = (const int*)  d_in[4];
    const int*   cols = (const int*)  d_in[5];
    float* out = (float*)d_out;

    // one-time attribute: prefer max L1 for the zero-smem gather kernels
    static int attr_set = 0;
    if (!attr_set) {
        cudaFuncSetAttribute(k_step, cudaFuncAttributePreferredSharedMemoryCarveout, 0);
        attr_set = 1;
    }

    k_hist   <<<1024 + Mv / 8, 256>>>(rows, x);       // 1  hist + x->T0 transpose
    k_scan1  <<<33, 1024>>>(kern);                    // 2  parallel scan + W conv
    k_scatter<<<Ev / 256, 256>>>(rows, cols, vals);   // 3
    k_step<<<Mv / 8, 256>>>(0, 0, 1, 1);   // 4  T1 = L T0
    k_step<<<Mv / 8, 256>>>(1, 0, 2, 0);   // 5  T2
    k_step<<<Mv / 8, 256>>>(2, 1, 3, 0);   // 6  T3  <- profiled slot
    k_step_fin<<<Mv / 8, 256>>>(bias, out);  // 7  T4 + GEMM + out
}